// round 3
// baseline (speedup 1.0000x reference)
#include <cuda_runtime.h>
#include <cstdint>

#define N_USERS 100000
#define N_ITEMS 60000
#define N_NODES (N_USERS + N_ITEMS)
#define EMB_DIM 128
#define VEC (EMB_DIM / 4)   // 32 float4 per row => one warp handles one row
#define N_EDGES 1500000

// Scratch (allocation-free rule: __device__ globals)
__device__ float g_xa[(size_t)N_NODES * EMB_DIM];
__device__ float g_xb[(size_t)N_NODES * EMB_DIM];
__device__ float g_invdeg[N_NODES];

// ---------------------------------------------------------------------------
// 1) degree count: one thread per edge, atomicAdd 1.0f at dst (exact ints)
__global__ void deg_kernel(const int* __restrict__ dst, float* __restrict__ deg) {
    int e = blockIdx.x * blockDim.x + threadIdx.x;
    if (e < N_EDGES) atomicAdd(&deg[dst[e]], 1.0f);
}

// 2) invert degree in place (isolated nodes -> 0)
__global__ void invdeg_kernel(float* __restrict__ deg) {
    int v = blockIdx.x * blockDim.x + threadIdx.x;
    if (v < N_NODES) {
        float d = deg[v];
        deg[v] = (d > 0.0f) ? (1.0f / d) : 0.0f;
    }
}

// 3) init: x0 = concat(user_emb, item_emb); out = 0.25 * x0
__global__ void init_kernel(const float4* __restrict__ ue,
                            const float4* __restrict__ ie,
                            float4* __restrict__ x,
                            float4* __restrict__ out) {
    long i = (long)blockIdx.x * blockDim.x + threadIdx.x;
    const long total = (long)N_NODES * VEC;
    if (i >= total) return;
    const long user_lim = (long)N_USERS * VEC;
    float4 v = (i < user_lim) ? ue[i] : ie[i - user_lim];
    x[i] = v;
    float4 o;
    o.x = 0.25f * v.x; o.y = 0.25f * v.y; o.z = 0.25f * v.z; o.w = 0.25f * v.w;
    out[i] = o;
}

// 4) scatter: warp per edge. Lane l loads float4 l of row src[e] (coalesced
//    512B row read, L2-resident) and red.global.add.v4.f32 into row dst[e].
__global__ void scatter_kernel(const int* __restrict__ src,
                               const int* __restrict__ dst,
                               const float4* __restrict__ xin,
                               float* __restrict__ xout) {
    long t = (long)blockIdx.x * blockDim.x + threadIdx.x;
    long e = t >> 5;
    int lane = (int)(t & 31);
    if (e >= N_EDGES) return;
    int s = src[e];            // uniform within warp -> L1 broadcast
    int d = dst[e];
    float4 v = __ldg(&xin[(long)s * VEC + lane]);
    float* p = xout + (long)d * EMB_DIM + lane * 4;
    asm volatile("red.global.add.v4.f32 [%0], {%1, %2, %3, %4};"
                 :: "l"(p), "f"(v.x), "f"(v.y), "f"(v.z), "f"(v.w)
                 : "memory");
}

// 5) scale by inv_deg (in place, becomes next layer's input) and accumulate
//    0.25 * x into out
__global__ void scale_acc_kernel(float4* __restrict__ x,
                                 float4* __restrict__ out,
                                 const float* __restrict__ invdeg) {
    long i = (long)blockIdx.x * blockDim.x + threadIdx.x;
    const long total = (long)N_NODES * VEC;
    if (i >= total) return;
    float s = __ldg(&invdeg[i >> 5]);   // i / VEC = node row
    float4 v = x[i];
    v.x *= s; v.y *= s; v.z *= s; v.w *= s;
    x[i] = v;
    float4 o = out[i];
    o.x += 0.25f * v.x; o.y += 0.25f * v.y; o.z += 0.25f * v.z; o.w += 0.25f * v.w;
    out[i] = o;
}

extern "C" void kernel_launch(void* const* d_in, const int* in_sizes, int n_in,
                              void* d_out, int out_size) {
    const float* ue = (const float*)d_in[0];           // [N_USERS, 128]
    const float* ie = (const float*)d_in[1];           // [N_ITEMS, 128]
    const int*   ei = (const int*)d_in[2];             // [2, N_EDGES] int32
    const int* src = ei;
    const int* dst = ei + N_EDGES;
    float* out = (float*)d_out;                        // [N_NODES, 128]

    float *xa = nullptr, *xb = nullptr, *invdeg = nullptr;
    cudaGetSymbolAddress((void**)&xa, g_xa);
    cudaGetSymbolAddress((void**)&xb, g_xb);
    cudaGetSymbolAddress((void**)&invdeg, g_invdeg);

    const int BT = 256;
    const long nvec = (long)N_NODES * VEC;             // 5,120,000 float4

    // degrees
    cudaMemsetAsync(invdeg, 0, N_NODES * sizeof(float));
    deg_kernel<<<(N_EDGES + BT - 1) / BT, BT>>>(dst, invdeg);
    invdeg_kernel<<<(N_NODES + BT - 1) / BT, BT>>>(invdeg);

    // layer 0
    init_kernel<<<(int)((nvec + BT - 1) / BT), BT>>>(
        (const float4*)ue, (const float4*)ie, (float4*)xa, (float4*)out);

    float* cur = xa;
    float* nxt = xb;
    for (int l = 0; l < 3; ++l) {
        cudaMemsetAsync(nxt, 0, (size_t)N_NODES * EMB_DIM * sizeof(float));
        long nthreads = (long)N_EDGES * 32;            // 48M threads
        unsigned int nblocks = (unsigned int)((nthreads + BT - 1) / BT);
        scatter_kernel<<<nblocks, BT>>>(src, dst, (const float4*)cur, nxt);
        scale_acc_kernel<<<(int)((nvec + BT - 1) / BT), BT>>>(
            (float4*)nxt, (float4*)out, invdeg);
        float* t = cur; cur = nxt; nxt = t;
    }
}

// round 4
// speedup vs baseline: 1.9302x; 1.9302x over previous
#include <cuda_runtime.h>
#include <cstdint>

#define N_USERS 100000
#define N_ITEMS 60000
#define N_NODES (N_USERS + N_ITEMS)
#define EMB_DIM 128
#define VEC (EMB_DIM / 4)        // 32 float4 per row => warp handles one row
#define N_EDGES 1500000
#define SCAN_BT 256
#define SCAN_BLOCKS (N_NODES / SCAN_BT)   // 160000/256 = 625 exact

// Scratch (__device__ globals per allocation-free rule)
__device__ float g_xa[(size_t)N_NODES * EMB_DIM];
__device__ float g_xb[(size_t)N_NODES * EMB_DIM];
__device__ float g_invdeg[N_NODES];
__device__ int   g_deg[N_NODES];
__device__ int   g_scanned[N_NODES];
__device__ int   g_blocksum[1024];
__device__ int   g_blockoff[1024];
__device__ int   g_rowptr[N_NODES + 1];
__device__ int   g_cursor[N_NODES];
__device__ int   g_csr[N_EDGES];

// ---------------------------------------------------------------------------
// 1) integer degree histogram over dst
__global__ void hist_kernel(const int* __restrict__ dst, int* __restrict__ deg) {
    int e = blockIdx.x * blockDim.x + threadIdx.x;
    if (e < N_EDGES) atomicAdd(&deg[dst[e]], 1);
}

// 2) block-local exclusive scan of deg; emit block sums; also inv_deg
__global__ void scan1_kernel(const int* __restrict__ deg,
                             int* __restrict__ scanned,
                             int* __restrict__ blocksum,
                             float* __restrict__ invdeg) {
    __shared__ int sh[SCAN_BT];
    int t = threadIdx.x;
    int idx = blockIdx.x * SCAN_BT + t;
    int v = deg[idx];
    invdeg[idx] = (v > 0) ? (1.0f / (float)v) : 0.0f;
    sh[t] = v;
    __syncthreads();
    // Hillis-Steele inclusive scan
    for (int off = 1; off < SCAN_BT; off <<= 1) {
        int add = (t >= off) ? sh[t - off] : 0;
        __syncthreads();
        sh[t] += add;
        __syncthreads();
    }
    scanned[idx] = sh[t] - v;                 // exclusive
    if (t == SCAN_BT - 1) blocksum[blockIdx.x] = sh[t];
}

// 3) single-block exclusive scan of the 625 block sums (padded to 1024)
__global__ void scan2_kernel(const int* __restrict__ blocksum,
                             int* __restrict__ blockoff) {
    __shared__ int sh[1024];
    int t = threadIdx.x;
    int v = (t < SCAN_BLOCKS) ? blocksum[t] : 0;
    sh[t] = v;
    __syncthreads();
    for (int off = 1; off < 1024; off <<= 1) {
        int add = (t >= off) ? sh[t - off] : 0;
        __syncthreads();
        sh[t] += add;
        __syncthreads();
    }
    blockoff[t] = sh[t] - v;                  // exclusive
}

// 4) finalize row_ptr and cursor
__global__ void scan3_kernel(const int* __restrict__ scanned,
                             const int* __restrict__ blockoff,
                             int* __restrict__ rowptr,
                             int* __restrict__ cursor) {
    int idx = blockIdx.x * blockDim.x + threadIdx.x;
    if (idx < N_NODES) {
        int r = scanned[idx] + blockoff[idx / SCAN_BT];
        rowptr[idx] = r;
        cursor[idx] = r;
    }
    if (idx == 0) rowptr[N_NODES] = N_EDGES;
}

// 5) bin edges by dst (arrival-order within a row; fp-order tolerance same
//    as the atomics the previous passing kernel used)
__global__ void permute_kernel(const int* __restrict__ src,
                               const int* __restrict__ dst,
                               int* __restrict__ cursor,
                               int* __restrict__ csr) {
    int e = blockIdx.x * blockDim.x + threadIdx.x;
    if (e < N_EDGES) {
        int pos = atomicAdd(&cursor[dst[e]], 1);
        csr[pos] = src[e];
    }
}

// 6) init: x0 = concat(user_emb, item_emb); out = 0.25 * x0
__global__ void init_kernel(const float4* __restrict__ ue,
                            const float4* __restrict__ ie,
                            float4* __restrict__ x,
                            float4* __restrict__ out) {
    long i = (long)blockIdx.x * blockDim.x + threadIdx.x;
    const long total = (long)N_NODES * VEC;
    if (i >= total) return;
    const long user_lim = (long)N_USERS * VEC;
    float4 v = (i < user_lim) ? ue[i] : ie[i - user_lim];
    x[i] = v;
    float4 o;
    o.x = 0.25f * v.x; o.y = 0.25f * v.y; o.z = 0.25f * v.z; o.w = 0.25f * v.w;
    out[i] = o;
}

// 7) fused SpMM + scale + out accumulation.
//    Warp per dst node: lane l owns float4 chunk l. 4-deep unrolled gather
//    keeps >=4 L2 loads in flight. Streaming (.cs) stores for xout/out so
//    the gather table stays L2-resident.
__global__ void __launch_bounds__(256)
spmm_kernel(const int* __restrict__ rowptr,
            const int* __restrict__ csr,
            const float* __restrict__ invdeg,
            const float4* __restrict__ xin,
            float4* __restrict__ xout,
            float4* __restrict__ out) {
    int w = (blockIdx.x * blockDim.x + threadIdx.x) >> 5;
    int lane = threadIdx.x & 31;
    if (w >= N_NODES) return;
    int beg = __ldg(&rowptr[w]);
    int end = __ldg(&rowptr[w + 1]);

    float4 a0 = {0,0,0,0}, a1 = {0,0,0,0}, a2 = {0,0,0,0}, a3 = {0,0,0,0};
    int i = beg;
    for (; i + 3 < end; i += 4) {
        int s0 = csr[i], s1 = csr[i+1], s2 = csr[i+2], s3 = csr[i+3];
        float4 v0 = __ldg(&xin[(long)s0 * VEC + lane]);
        float4 v1 = __ldg(&xin[(long)s1 * VEC + lane]);
        float4 v2 = __ldg(&xin[(long)s2 * VEC + lane]);
        float4 v3 = __ldg(&xin[(long)s3 * VEC + lane]);
        a0.x += v0.x; a0.y += v0.y; a0.z += v0.z; a0.w += v0.w;
        a1.x += v1.x; a1.y += v1.y; a1.z += v1.z; a1.w += v1.w;
        a2.x += v2.x; a2.y += v2.y; a2.z += v2.z; a2.w += v2.w;
        a3.x += v3.x; a3.y += v3.y; a3.z += v3.z; a3.w += v3.w;
    }
    for (; i < end; ++i) {
        int s = csr[i];
        float4 v = __ldg(&xin[(long)s * VEC + lane]);
        a0.x += v.x; a0.y += v.y; a0.z += v.z; a0.w += v.w;
    }
    float sc = __ldg(&invdeg[w]);
    float4 r;
    r.x = (a0.x + a1.x + a2.x + a3.x) * sc;
    r.y = (a0.y + a1.y + a2.y + a3.y) * sc;
    r.z = (a0.z + a1.z + a2.z + a3.z) * sc;
    r.w = (a0.w + a1.w + a2.w + a3.w) * sc;

    long o = (long)w * VEC + lane;
    __stcs(&xout[o], r);                       // streaming: evict-first
    float4 ov = __ldcs(&out[o]);
    ov.x += 0.25f * r.x; ov.y += 0.25f * r.y;
    ov.z += 0.25f * r.z; ov.w += 0.25f * r.w;
    __stcs(&out[o], ov);
}

extern "C" void kernel_launch(void* const* d_in, const int* in_sizes, int n_in,
                              void* d_out, int out_size) {
    const float* ue = (const float*)d_in[0];           // [N_USERS, 128]
    const float* ie = (const float*)d_in[1];           // [N_ITEMS, 128]
    const int*   ei = (const int*)d_in[2];             // [2, N_EDGES] int32
    const int* src = ei;
    const int* dst = ei + N_EDGES;
    float* out = (float*)d_out;                        // [N_NODES, 128]

    float *xa, *xb, *invdeg;
    int *deg, *scanned, *blocksum, *blockoff, *rowptr, *cursor, *csr;
    cudaGetSymbolAddress((void**)&xa, g_xa);
    cudaGetSymbolAddress((void**)&xb, g_xb);
    cudaGetSymbolAddress((void**)&invdeg, g_invdeg);
    cudaGetSymbolAddress((void**)&deg, g_deg);
    cudaGetSymbolAddress((void**)&scanned, g_scanned);
    cudaGetSymbolAddress((void**)&blocksum, g_blocksum);
    cudaGetSymbolAddress((void**)&blockoff, g_blockoff);
    cudaGetSymbolAddress((void**)&rowptr, g_rowptr);
    cudaGetSymbolAddress((void**)&cursor, g_cursor);
    cudaGetSymbolAddress((void**)&csr, g_csr);

    const int BT = 256;
    const long nvec = (long)N_NODES * VEC;             // 5,120,000 float4

    // ---- CSR build ----
    cudaMemsetAsync(deg, 0, N_NODES * sizeof(int));
    hist_kernel<<<(N_EDGES + BT - 1) / BT, BT>>>(dst, deg);
    scan1_kernel<<<SCAN_BLOCKS, SCAN_BT>>>(deg, scanned, blocksum, invdeg);
    scan2_kernel<<<1, 1024>>>(blocksum, blockoff);
    scan3_kernel<<<(N_NODES + BT - 1) / BT, BT>>>(scanned, blockoff, rowptr, cursor);
    permute_kernel<<<(N_EDGES + BT - 1) / BT, BT>>>(src, dst, cursor, csr);

    // ---- layer 0 ----
    init_kernel<<<(int)((nvec + BT - 1) / BT), BT>>>(
        (const float4*)ue, (const float4*)ie, (float4*)xa, (float4*)out);

    // ---- 3 propagation layers, fully fused ----
    float* cur = xa;
    float* nxt = xb;
    const int spmm_blocks = (N_NODES * 32 + BT - 1) / BT;   // warp per node
    for (int l = 0; l < 3; ++l) {
        spmm_kernel<<<spmm_blocks, BT>>>(rowptr, csr, invdeg,
                                         (const float4*)cur,
                                         (float4*)nxt, (float4*)out);
        float* t = cur; cur = nxt; nxt = t;
    }
}

// round 5
// speedup vs baseline: 2.3408x; 1.2127x over previous
#include <cuda_runtime.h>
#include <cstdint>

#define N_USERS 100000
#define N_ITEMS 60000
#define N_NODES (N_USERS + N_ITEMS)
#define EMB_DIM 128
#define VEC (EMB_DIM / 4)        // 32 float4 per row => warp handles one row
#define N_EDGES 1500000
#define SCAN_BT 256
#define SCAN_BLOCKS (N_NODES / SCAN_BT)   // 160000/256 = 625 exact

// Scratch (__device__ globals per allocation-free rule)
__device__ float g_xa[(size_t)N_NODES * EMB_DIM];   // x1
__device__ float g_xb[(size_t)N_NODES * EMB_DIM];   // x2
__device__ float g_invdeg[N_NODES];
__device__ int   g_deg[N_NODES];
__device__ int   g_scanned[N_NODES];
__device__ int   g_blocksum[1024];
__device__ int   g_blockoff[1024];
__device__ int   g_rowptr[N_NODES + 1];
__device__ int   g_cursor[N_NODES];
__device__ int   g_csr[N_EDGES];

// ---------------------------------------------------------------------------
// 1) integer degree histogram over dst
__global__ void hist_kernel(const int* __restrict__ dst, int* __restrict__ deg) {
    int e = blockIdx.x * blockDim.x + threadIdx.x;
    if (e < N_EDGES) atomicAdd(&deg[dst[e]], 1);
}

// 2) block-local exclusive scan of deg; emit block sums; also inv_deg
__global__ void scan1_kernel(const int* __restrict__ deg,
                             int* __restrict__ scanned,
                             int* __restrict__ blocksum,
                             float* __restrict__ invdeg) {
    __shared__ int sh[SCAN_BT];
    int t = threadIdx.x;
    int idx = blockIdx.x * SCAN_BT + t;
    int v = deg[idx];
    invdeg[idx] = (v > 0) ? (1.0f / (float)v) : 0.0f;
    sh[t] = v;
    __syncthreads();
    for (int off = 1; off < SCAN_BT; off <<= 1) {
        int add = (t >= off) ? sh[t - off] : 0;
        __syncthreads();
        sh[t] += add;
        __syncthreads();
    }
    scanned[idx] = sh[t] - v;                 // exclusive
    if (t == SCAN_BT - 1) blocksum[blockIdx.x] = sh[t];
}

// 3) single-block exclusive scan of the 625 block sums (padded to 1024)
__global__ void scan2_kernel(const int* __restrict__ blocksum,
                             int* __restrict__ blockoff) {
    __shared__ int sh[1024];
    int t = threadIdx.x;
    int v = (t < SCAN_BLOCKS) ? blocksum[t] : 0;
    sh[t] = v;
    __syncthreads();
    for (int off = 1; off < 1024; off <<= 1) {
        int add = (t >= off) ? sh[t - off] : 0;
        __syncthreads();
        sh[t] += add;
        __syncthreads();
    }
    blockoff[t] = sh[t] - v;                  // exclusive
}

// 4) finalize row_ptr and cursor
__global__ void scan3_kernel(const int* __restrict__ scanned,
                             const int* __restrict__ blockoff,
                             int* __restrict__ rowptr,
                             int* __restrict__ cursor) {
    int idx = blockIdx.x * blockDim.x + threadIdx.x;
    if (idx < N_NODES) {
        int r = scanned[idx] + blockoff[idx / SCAN_BT];
        rowptr[idx] = r;
        cursor[idx] = r;
    }
    if (idx == 0) rowptr[N_NODES] = N_EDGES;
}

// 5) bin edges by dst
__global__ void permute_kernel(const int* __restrict__ src,
                               const int* __restrict__ dst,
                               int* __restrict__ cursor,
                               int* __restrict__ csr) {
    int e = blockIdx.x * blockDim.x + threadIdx.x;
    if (e < N_EDGES) {
        int pos = atomicAdd(&cursor[dst[e]], 1);
        csr[pos] = src[e];
    }
}

// ---------------------------------------------------------------------------
// x0 gather: node s row chunk `lane` straight from the input embeddings
__device__ __forceinline__ float4 gather_x0(const float4* __restrict__ ue,
                                            const float4* __restrict__ ie,
                                            int s, int lane) {
    return (s < N_USERS) ? __ldg(&ue[(long)s * VEC + lane])
                         : __ldg(&ie[(long)(s - N_USERS) * VEC + lane]);
}

// Warp-per-node mean aggregation core: returns inv_deg-scaled row sum.
// MODE 0: gather from xin.  MODE 1: gather from concat(ue,ie).
template <int MODE>
__device__ __forceinline__ float4 row_mean(const int* __restrict__ rowptr,
                                           const int* __restrict__ csr,
                                           const float* __restrict__ invdeg,
                                           const float4* __restrict__ xin,
                                           const float4* __restrict__ ue,
                                           const float4* __restrict__ ie,
                                           int w, int lane) {
    int beg = __ldg(&rowptr[w]);
    int end = __ldg(&rowptr[w + 1]);
    float4 a0 = {0,0,0,0}, a1 = {0,0,0,0}, a2 = {0,0,0,0}, a3 = {0,0,0,0};
    int i = beg;
    for (; i + 3 < end; i += 4) {
        int s0 = csr[i], s1 = csr[i+1], s2 = csr[i+2], s3 = csr[i+3];
        float4 v0, v1, v2, v3;
        if (MODE == 1) {
            v0 = gather_x0(ue, ie, s0, lane);
            v1 = gather_x0(ue, ie, s1, lane);
            v2 = gather_x0(ue, ie, s2, lane);
            v3 = gather_x0(ue, ie, s3, lane);
        } else {
            v0 = __ldg(&xin[(long)s0 * VEC + lane]);
            v1 = __ldg(&xin[(long)s1 * VEC + lane]);
            v2 = __ldg(&xin[(long)s2 * VEC + lane]);
            v3 = __ldg(&xin[(long)s3 * VEC + lane]);
        }
        a0.x += v0.x; a0.y += v0.y; a0.z += v0.z; a0.w += v0.w;
        a1.x += v1.x; a1.y += v1.y; a1.z += v1.z; a1.w += v1.w;
        a2.x += v2.x; a2.y += v2.y; a2.z += v2.z; a2.w += v2.w;
        a3.x += v3.x; a3.y += v3.y; a3.z += v3.z; a3.w += v3.w;
    }
    for (; i < end; ++i) {
        int s = csr[i];
        float4 v = (MODE == 1) ? gather_x0(ue, ie, s, lane)
                               : __ldg(&xin[(long)s * VEC + lane]);
        a0.x += v.x; a0.y += v.y; a0.z += v.z; a0.w += v.w;
    }
    float sc = __ldg(&invdeg[w]);
    float4 r;
    r.x = (a0.x + a1.x + a2.x + a3.x) * sc;
    r.y = (a0.y + a1.y + a2.y + a3.y) * sc;
    r.z = (a0.z + a1.z + a2.z + a3.z) * sc;
    r.w = (a0.w + a1.w + a2.w + a3.w) * sc;
    return r;
}

// Layer 1: x1 = A~ @ x0, gathering straight from ue/ie (no init copy pass)
__global__ void __launch_bounds__(256)
layer1_kernel(const int* __restrict__ rowptr, const int* __restrict__ csr,
              const float* __restrict__ invdeg,
              const float4* __restrict__ ue, const float4* __restrict__ ie,
              float4* __restrict__ x1) {
    int w = (blockIdx.x * blockDim.x + threadIdx.x) >> 5;
    int lane = threadIdx.x & 31;
    if (w >= N_NODES) return;
    float4 r = row_mean<1>(rowptr, csr, invdeg, nullptr, ue, ie, w, lane);
    __stcs(&x1[(long)w * VEC + lane], r);
}

// Layer 2: x2 = A~ @ x1
__global__ void __launch_bounds__(256)
layer2_kernel(const int* __restrict__ rowptr, const int* __restrict__ csr,
              const float* __restrict__ invdeg,
              const float4* __restrict__ x1, float4* __restrict__ x2) {
    int w = (blockIdx.x * blockDim.x + threadIdx.x) >> 5;
    int lane = threadIdx.x & 31;
    if (w >= N_NODES) return;
    float4 r = row_mean<0>(rowptr, csr, invdeg, x1, nullptr, nullptr, w, lane);
    __stcs(&x2[(long)w * VEC + lane], r);
}

// Layer 3 fused finale: r = A~ @ x2 (kept in regs only);
// out = 0.25*(x0 + x1 + x2 + r). x2 row is L2-hot (it's the gather table);
// x0/x1 reads and out write are streaming.
__global__ void __launch_bounds__(256)
layer3_kernel(const int* __restrict__ rowptr, const int* __restrict__ csr,
              const float* __restrict__ invdeg,
              const float4* __restrict__ ue, const float4* __restrict__ ie,
              const float4* __restrict__ x1, const float4* __restrict__ x2,
              float4* __restrict__ out) {
    int w = (blockIdx.x * blockDim.x + threadIdx.x) >> 5;
    int lane = threadIdx.x & 31;
    if (w >= N_NODES) return;
    float4 r = row_mean<0>(rowptr, csr, invdeg, x2, nullptr, nullptr, w, lane);
    long o = (long)w * VEC + lane;
    float4 v0 = (w < N_USERS) ? __ldcs(&ue[o]) : __ldcs(&ie[o - (long)N_USERS * VEC]);
    float4 v1 = __ldcs(&x1[o]);
    float4 v2 = __ldg(&x2[o]);       // hot in L2
    float4 ov;
    ov.x = 0.25f * (v0.x + v1.x + v2.x + r.x);
    ov.y = 0.25f * (v0.y + v1.y + v2.y + r.y);
    ov.z = 0.25f * (v0.z + v1.z + v2.z + r.z);
    ov.w = 0.25f * (v0.w + v1.w + v2.w + r.w);
    __stcs(&out[o], ov);
}

extern "C" void kernel_launch(void* const* d_in, const int* in_sizes, int n_in,
                              void* d_out, int out_size) {
    const float* ue = (const float*)d_in[0];           // [N_USERS, 128]
    const float* ie = (const float*)d_in[1];           // [N_ITEMS, 128]
    const int*   ei = (const int*)d_in[2];             // [2, N_EDGES] int32
    const int* src = ei;
    const int* dst = ei + N_EDGES;
    float* out = (float*)d_out;                        // [N_NODES, 128]

    float *xa, *xb, *invdeg;
    int *deg, *scanned, *blocksum, *blockoff, *rowptr, *cursor, *csr;
    cudaGetSymbolAddress((void**)&xa, g_xa);
    cudaGetSymbolAddress((void**)&xb, g_xb);
    cudaGetSymbolAddress((void**)&invdeg, g_invdeg);
    cudaGetSymbolAddress((void**)&deg, g_deg);
    cudaGetSymbolAddress((void**)&scanned, g_scanned);
    cudaGetSymbolAddress((void**)&blocksum, g_blocksum);
    cudaGetSymbolAddress((void**)&blockoff, g_blockoff);
    cudaGetSymbolAddress((void**)&rowptr, g_rowptr);
    cudaGetSymbolAddress((void**)&cursor, g_cursor);
    cudaGetSymbolAddress((void**)&csr, g_csr);

    const int BT = 256;

    // ---- CSR build ----
    cudaMemsetAsync(deg, 0, N_NODES * sizeof(int));
    hist_kernel<<<(N_EDGES + BT - 1) / BT, BT>>>(dst, deg);
    scan1_kernel<<<SCAN_BLOCKS, SCAN_BT>>>(deg, scanned, blocksum, invdeg);
    scan2_kernel<<<1, 1024>>>(blocksum, blockoff);
    scan3_kernel<<<(N_NODES + BT - 1) / BT, BT>>>(scanned, blockoff, rowptr, cursor);
    permute_kernel<<<(N_EDGES + BT - 1) / BT, BT>>>(src, dst, cursor, csr);

    // ---- 3 propagation layers (warp per node) ----
    const int blocks = (N_NODES * 32 + BT - 1) / BT;
    layer1_kernel<<<blocks, BT>>>(rowptr, csr, invdeg,
                                  (const float4*)ue, (const float4*)ie,
                                  (float4*)xa);
    layer2_kernel<<<blocks, BT>>>(rowptr, csr, invdeg,
                                  (const float4*)xa, (float4*)xb);
    layer3_kernel<<<blocks, BT>>>(rowptr, csr, invdeg,
                                  (const float4*)ue, (const float4*)ie,
                                  (const float4*)xa, (const float4*)xb,
                                  (float4*)out);
}

// round 6
// speedup vs baseline: 2.9391x; 1.2556x over previous
#include <cuda_runtime.h>
#include <cuda_fp16.h>
#include <cstdint>

#define N_USERS 100000
#define N_ITEMS 60000
#define N_NODES (N_USERS + N_ITEMS)
#define EMB_DIM 128
#define VEC (EMB_DIM / 4)        // 32 float4 (fp32) or uint2 (fp16x4) per row
#define N_EDGES 1500000
#define SCAN_BT 256
#define SCAN_BLOCKS (N_NODES / SCAN_BT)   // 625 exact

// Scratch (__device__ globals per allocation-free rule)
// x1/x2 stored as fp16: row = 128 halfs = 32 uint2 (lane l owns elems 4l..4l+3)
__device__ uint2 g_x1[(size_t)N_NODES * VEC];
__device__ uint2 g_x2[(size_t)N_NODES * VEC];
__device__ float g_invdeg[N_NODES];
__device__ int   g_deg[N_NODES];
__device__ int   g_scanned[N_NODES];
__device__ int   g_blocksum[1024];
__device__ int   g_blockoff[1024];
__device__ int   g_rowptr[N_NODES + 1];
__device__ int   g_cursor[N_NODES];
__device__ int   g_csr[N_EDGES];

// ---------------------------------------------------------------------------
__global__ void hist_kernel(const int* __restrict__ dst, int* __restrict__ deg) {
    int e = blockIdx.x * blockDim.x + threadIdx.x;
    if (e < N_EDGES) atomicAdd(&deg[dst[e]], 1);
}

__global__ void scan1_kernel(const int* __restrict__ deg,
                             int* __restrict__ scanned,
                             int* __restrict__ blocksum,
                             float* __restrict__ invdeg) {
    __shared__ int sh[SCAN_BT];
    int t = threadIdx.x;
    int idx = blockIdx.x * SCAN_BT + t;
    int v = deg[idx];
    invdeg[idx] = (v > 0) ? (1.0f / (float)v) : 0.0f;
    sh[t] = v;
    __syncthreads();
    for (int off = 1; off < SCAN_BT; off <<= 1) {
        int add = (t >= off) ? sh[t - off] : 0;
        __syncthreads();
        sh[t] += add;
        __syncthreads();
    }
    scanned[idx] = sh[t] - v;
    if (t == SCAN_BT - 1) blocksum[blockIdx.x] = sh[t];
}

__global__ void scan2_kernel(const int* __restrict__ blocksum,
                             int* __restrict__ blockoff) {
    __shared__ int sh[1024];
    int t = threadIdx.x;
    int v = (t < SCAN_BLOCKS) ? blocksum[t] : 0;
    sh[t] = v;
    __syncthreads();
    for (int off = 1; off < 1024; off <<= 1) {
        int add = (t >= off) ? sh[t - off] : 0;
        __syncthreads();
        sh[t] += add;
        __syncthreads();
    }
    blockoff[t] = sh[t] - v;
}

__global__ void scan3_kernel(const int* __restrict__ scanned,
                             const int* __restrict__ blockoff,
                             int* __restrict__ rowptr,
                             int* __restrict__ cursor) {
    int idx = blockIdx.x * blockDim.x + threadIdx.x;
    if (idx < N_NODES) {
        int r = scanned[idx] + blockoff[idx / SCAN_BT];
        rowptr[idx] = r;
        cursor[idx] = r;
    }
    if (idx == 0) rowptr[N_NODES] = N_EDGES;
}

__global__ void permute_kernel(const int* __restrict__ src,
                               const int* __restrict__ dst,
                               int* __restrict__ cursor,
                               int* __restrict__ csr) {
    int e = blockIdx.x * blockDim.x + threadIdx.x;
    if (e < N_EDGES) {
        int pos = atomicAdd(&cursor[dst[e]], 1);
        csr[pos] = src[e];
    }
}

// ---------------------------------------------------------------------------
__device__ __forceinline__ void acc4(float4& a, float4 v) {
    a.x += v.x; a.y += v.y; a.z += v.z; a.w += v.w;
}
__device__ __forceinline__ float4 h4_to_f4(uint2 u) {
    float2 lo = __half22float2(*reinterpret_cast<__half2*>(&u.x));
    float2 hi = __half22float2(*reinterpret_cast<__half2*>(&u.y));
    float4 r; r.x = lo.x; r.y = lo.y; r.z = hi.x; r.w = hi.y;
    return r;
}
__device__ __forceinline__ uint2 f4_to_h4(float4 v) {
    __half2 lo = __floats2half2_rn(v.x, v.y);
    __half2 hi = __floats2half2_rn(v.z, v.w);
    uint2 u;
    u.x = *reinterpret_cast<uint32_t*>(&lo);
    u.y = *reinterpret_cast<uint32_t*>(&hi);
    return u;
}
__device__ __forceinline__ float4 gather_x0(const float4* __restrict__ ue,
                                            const float4* __restrict__ ie,
                                            int s, int lane) {
    return (s < N_USERS) ? __ldg(&ue[(long)s * VEC + lane])
                         : __ldg(&ie[(long)(s - N_USERS) * VEC + lane]);
}

// Warp-per-node mean. MODE 1: gather fp32 from concat(ue,ie). MODE 0: fp16 xin.
template <int MODE>
__device__ __forceinline__ float4 row_mean(const int* __restrict__ rowptr,
                                           const int* __restrict__ csr,
                                           const float* __restrict__ invdeg,
                                           const uint2* __restrict__ xin,
                                           const float4* __restrict__ ue,
                                           const float4* __restrict__ ie,
                                           int w, int lane) {
    int beg = __ldg(&rowptr[w]);
    int end = __ldg(&rowptr[w + 1]);
    float4 a0 = {0,0,0,0}, a1 = {0,0,0,0}, a2 = {0,0,0,0}, a3 = {0,0,0,0};
    int i = beg;
    for (; i + 3 < end; i += 4) {
        int s0 = csr[i], s1 = csr[i+1], s2 = csr[i+2], s3 = csr[i+3];
        if (MODE == 1) {
            acc4(a0, gather_x0(ue, ie, s0, lane));
            acc4(a1, gather_x0(ue, ie, s1, lane));
            acc4(a2, gather_x0(ue, ie, s2, lane));
            acc4(a3, gather_x0(ue, ie, s3, lane));
        } else {
            uint2 u0 = __ldg(&xin[(long)s0 * VEC + lane]);
            uint2 u1 = __ldg(&xin[(long)s1 * VEC + lane]);
            uint2 u2 = __ldg(&xin[(long)s2 * VEC + lane]);
            uint2 u3 = __ldg(&xin[(long)s3 * VEC + lane]);
            acc4(a0, h4_to_f4(u0));
            acc4(a1, h4_to_f4(u1));
            acc4(a2, h4_to_f4(u2));
            acc4(a3, h4_to_f4(u3));
        }
    }
    for (; i < end; ++i) {
        int s = csr[i];
        if (MODE == 1) acc4(a0, gather_x0(ue, ie, s, lane));
        else           acc4(a0, h4_to_f4(__ldg(&xin[(long)s * VEC + lane])));
    }
    float sc = __ldg(&invdeg[w]);
    float4 r;
    r.x = (a0.x + a1.x + a2.x + a3.x) * sc;
    r.y = (a0.y + a1.y + a2.y + a3.y) * sc;
    r.z = (a0.z + a1.z + a2.z + a3.z) * sc;
    r.w = (a0.w + a1.w + a2.w + a3.w) * sc;
    return r;
}

// Layer 1: x1 (fp16) = A~ @ x0 (fp32 inputs, no init pass)
__global__ void __launch_bounds__(256)
layer1_kernel(const int* __restrict__ rowptr, const int* __restrict__ csr,
              const float* __restrict__ invdeg,
              const float4* __restrict__ ue, const float4* __restrict__ ie,
              uint2* __restrict__ x1) {
    int w = (blockIdx.x * blockDim.x + threadIdx.x) >> 5;
    int lane = threadIdx.x & 31;
    if (w >= N_NODES) return;
    float4 r = row_mean<1>(rowptr, csr, invdeg, nullptr, ue, ie, w, lane);
    __stcs(&x1[(long)w * VEC + lane], f4_to_h4(r));
}

// Layer 2: x2 (fp16) = A~ @ x1
__global__ void __launch_bounds__(256)
layer2_kernel(const int* __restrict__ rowptr, const int* __restrict__ csr,
              const float* __restrict__ invdeg,
              const uint2* __restrict__ x1, uint2* __restrict__ x2) {
    int w = (blockIdx.x * blockDim.x + threadIdx.x) >> 5;
    int lane = threadIdx.x & 31;
    if (w >= N_NODES) return;
    float4 r = row_mean<0>(rowptr, csr, invdeg, x1, nullptr, nullptr, w, lane);
    __stcs(&x2[(long)w * VEC + lane], f4_to_h4(r));
}

// Layer 3 fused finale: r = A~ @ x2 (regs only); out = 0.25*(x0+x1+x2+r)
__global__ void __launch_bounds__(256)
layer3_kernel(const int* __restrict__ rowptr, const int* __restrict__ csr,
              const float* __restrict__ invdeg,
              const float4* __restrict__ ue, const float4* __restrict__ ie,
              const uint2* __restrict__ x1, const uint2* __restrict__ x2,
              float4* __restrict__ out) {
    int w = (blockIdx.x * blockDim.x + threadIdx.x) >> 5;
    int lane = threadIdx.x & 31;
    if (w >= N_NODES) return;
    float4 r = row_mean<0>(rowptr, csr, invdeg, x2, nullptr, nullptr, w, lane);
    long o = (long)w * VEC + lane;
    float4 v0 = (w < N_USERS) ? __ldcs(&ue[o]) : __ldcs(&ie[o - (long)N_USERS * VEC]);
    float4 v1 = h4_to_f4(__ldcs(&x1[o]));
    float4 v2 = h4_to_f4(__ldg(&x2[o]));      // hot in L2 (gather table)
    float4 ov;
    ov.x = 0.25f * (v0.x + v1.x + v2.x + r.x);
    ov.y = 0.25f * (v0.y + v1.y + v2.y + r.y);
    ov.z = 0.25f * (v0.z + v1.z + v2.z + r.z);
    ov.w = 0.25f * (v0.w + v1.w + v2.w + r.w);
    __stcs(&out[o], ov);
}

extern "C" void kernel_launch(void* const* d_in, const int* in_sizes, int n_in,
                              void* d_out, int out_size) {
    const float* ue = (const float*)d_in[0];           // [N_USERS, 128]
    const float* ie = (const float*)d_in[1];           // [N_ITEMS, 128]
    const int*   ei = (const int*)d_in[2];             // [2, N_EDGES] int32
    const int* src = ei;
    const int* dst = ei + N_EDGES;
    float* out = (float*)d_out;                        // [N_NODES, 128] fp32

    uint2 *x1, *x2;
    float *invdeg;
    int *deg, *scanned, *blocksum, *blockoff, *rowptr, *cursor, *csr;
    cudaGetSymbolAddress((void**)&x1, g_x1);
    cudaGetSymbolAddress((void**)&x2, g_x2);
    cudaGetSymbolAddress((void**)&invdeg, g_invdeg);
    cudaGetSymbolAddress((void**)&deg, g_deg);
    cudaGetSymbolAddress((void**)&scanned, g_scanned);
    cudaGetSymbolAddress((void**)&blocksum, g_blocksum);
    cudaGetSymbolAddress((void**)&blockoff, g_blockoff);
    cudaGetSymbolAddress((void**)&rowptr, g_rowptr);
    cudaGetSymbolAddress((void**)&cursor, g_cursor);
    cudaGetSymbolAddress((void**)&csr, g_csr);

    const int BT = 256;

    // ---- CSR build ----
    cudaMemsetAsync(deg, 0, N_NODES * sizeof(int));
    hist_kernel<<<(N_EDGES + BT - 1) / BT, BT>>>(dst, deg);
    scan1_kernel<<<SCAN_BLOCKS, SCAN_BT>>>(deg, scanned, blocksum, invdeg);
    scan2_kernel<<<1, 1024>>>(blocksum, blockoff);
    scan3_kernel<<<(N_NODES + BT - 1) / BT, BT>>>(scanned, blockoff, rowptr, cursor);
    permute_kernel<<<(N_EDGES + BT - 1) / BT, BT>>>(src, dst, cursor, csr);

    // ---- 3 propagation layers (warp per node) ----
    const int blocks = (N_NODES * 32 + BT - 1) / BT;
    layer1_kernel<<<blocks, BT>>>(rowptr, csr, invdeg,
                                  (const float4*)ue, (const float4*)ie, x1);
    layer2_kernel<<<blocks, BT>>>(rowptr, csr, invdeg, x1, x2);
    layer3_kernel<<<blocks, BT>>>(rowptr, csr, invdeg,
                                  (const float4*)ue, (const float4*)ie,
                                  x1, x2, (float4*)out);
}

// round 7
// speedup vs baseline: 2.9611x; 1.0075x over previous
#include <cuda_runtime.h>
#include <cuda_fp16.h>
#include <cstdint>

#define N_USERS 100000
#define N_ITEMS 60000
#define N_NODES (N_USERS + N_ITEMS)
#define EMB_DIM 128
#define VEC (EMB_DIM / 4)        // 32 chunks/row: float4 (fp32) or uint2 (fp16x4)
#define N_EDGES 1500000
#define SCAN_BT 256
#define SCAN_BLOCKS (N_NODES / SCAN_BT)   // 625 exact

// Scratch (__device__ globals per allocation-free rule)
// fp16 tables: row = 128 halfs = 32 uint2 (lane l owns elems 4l..4l+3)
__device__ uint2 g_x0h[(size_t)N_NODES * VEC];
__device__ uint2 g_x1[(size_t)N_NODES * VEC];
__device__ uint2 g_x2[(size_t)N_NODES * VEC];
__device__ float g_invdeg[N_NODES];
__device__ int   g_deg[N_NODES];
__device__ int   g_scanned[N_NODES];
__device__ int   g_blocksum[1024];
__device__ int   g_blockoff[1024];
__device__ int   g_rowptr[N_NODES + 1];
__device__ int   g_cursor[N_NODES];
__device__ int   g_csr[N_EDGES];

// ---------------------------------------------------------------------------
__global__ void hist_kernel(const int* __restrict__ dst, int* __restrict__ deg) {
    int e = blockIdx.x * blockDim.x + threadIdx.x;
    if (e < N_EDGES) atomicAdd(&deg[dst[e]], 1);
}

__global__ void scan1_kernel(const int* __restrict__ deg,
                             int* __restrict__ scanned,
                             int* __restrict__ blocksum,
                             float* __restrict__ invdeg) {
    __shared__ int sh[SCAN_BT];
    int t = threadIdx.x;
    int idx = blockIdx.x * SCAN_BT + t;
    int v = deg[idx];
    invdeg[idx] = (v > 0) ? (1.0f / (float)v) : 0.0f;
    sh[t] = v;
    __syncthreads();
    for (int off = 1; off < SCAN_BT; off <<= 1) {
        int add = (t >= off) ? sh[t - off] : 0;
        __syncthreads();
        sh[t] += add;
        __syncthreads();
    }
    scanned[idx] = sh[t] - v;
    if (t == SCAN_BT - 1) blocksum[blockIdx.x] = sh[t];
}

__global__ void scan2_kernel(const int* __restrict__ blocksum,
                             int* __restrict__ blockoff) {
    __shared__ int sh[1024];
    int t = threadIdx.x;
    int v = (t < SCAN_BLOCKS) ? blocksum[t] : 0;
    sh[t] = v;
    __syncthreads();
    for (int off = 1; off < 1024; off <<= 1) {
        int add = (t >= off) ? sh[t - off] : 0;
        __syncthreads();
        sh[t] += add;
        __syncthreads();
    }
    blockoff[t] = sh[t] - v;
}

__global__ void scan3_kernel(const int* __restrict__ scanned,
                             const int* __restrict__ blockoff,
                             int* __restrict__ rowptr,
                             int* __restrict__ cursor) {
    int idx = blockIdx.x * blockDim.x + threadIdx.x;
    if (idx < N_NODES) {
        int r = scanned[idx] + blockoff[idx / SCAN_BT];
        rowptr[idx] = r;
        cursor[idx] = r;
    }
    if (idx == 0) rowptr[N_NODES] = N_EDGES;
}

__global__ void permute_kernel(const int* __restrict__ src,
                               const int* __restrict__ dst,
                               int* __restrict__ cursor,
                               int* __restrict__ csr) {
    int e = blockIdx.x * blockDim.x + threadIdx.x;
    if (e < N_EDGES) {
        int pos = atomicAdd(&cursor[dst[e]], 1);
        csr[pos] = src[e];
    }
}

// ---------------------------------------------------------------------------
__device__ __forceinline__ void acc4(float4& a, float4 v) {
    a.x += v.x; a.y += v.y; a.z += v.z; a.w += v.w;
}
__device__ __forceinline__ float4 h4_to_f4(uint2 u) {
    float2 lo = __half22float2(*reinterpret_cast<__half2*>(&u.x));
    float2 hi = __half22float2(*reinterpret_cast<__half2*>(&u.y));
    float4 r; r.x = lo.x; r.y = lo.y; r.z = hi.x; r.w = hi.y;
    return r;
}
__device__ __forceinline__ uint2 f4_to_h4(float4 v) {
    __half2 lo = __floats2half2_rn(v.x, v.y);
    __half2 hi = __floats2half2_rn(v.z, v.w);
    uint2 u;
    u.x = *reinterpret_cast<uint32_t*>(&lo);
    u.y = *reinterpret_cast<uint32_t*>(&hi);
    return u;
}

// convert concat(ue, ie) fp32 -> fp16 table (streaming both ways)
__global__ void convert_kernel(const float4* __restrict__ ue,
                               const float4* __restrict__ ie,
                               uint2* __restrict__ x0h) {
    long i = (long)blockIdx.x * blockDim.x + threadIdx.x;
    const long total = (long)N_NODES * VEC;
    if (i >= total) return;
    const long user_lim = (long)N_USERS * VEC;
    float4 v = (i < user_lim) ? __ldcs(&ue[i]) : __ldcs(&ie[i - user_lim]);
    __stcs(&x0h[i], f4_to_h4(v));
}

// Warp-per-node mean over an fp16 table. 8-deep unrolled gather: 8 loads in
// flight per warp before any accumulation (hides ~234cyc L2 latency).
__device__ __forceinline__ float4 row_mean_h(const int* __restrict__ rowptr,
                                             const int* __restrict__ csr,
                                             const float* __restrict__ invdeg,
                                             const uint2* __restrict__ xin,
                                             int w, int lane) {
    int beg = __ldg(&rowptr[w]);
    int end = __ldg(&rowptr[w + 1]);
    float4 a0 = {0,0,0,0}, a1 = {0,0,0,0}, a2 = {0,0,0,0}, a3 = {0,0,0,0};
    int i = beg;
    for (; i + 7 < end; i += 8) {
        int s0 = csr[i],   s1 = csr[i+1], s2 = csr[i+2], s3 = csr[i+3];
        int s4 = csr[i+4], s5 = csr[i+5], s6 = csr[i+6], s7 = csr[i+7];
        uint2 u0 = __ldg(&xin[(long)s0 * VEC + lane]);
        uint2 u1 = __ldg(&xin[(long)s1 * VEC + lane]);
        uint2 u2 = __ldg(&xin[(long)s2 * VEC + lane]);
        uint2 u3 = __ldg(&xin[(long)s3 * VEC + lane]);
        uint2 u4 = __ldg(&xin[(long)s4 * VEC + lane]);
        uint2 u5 = __ldg(&xin[(long)s5 * VEC + lane]);
        uint2 u6 = __ldg(&xin[(long)s6 * VEC + lane]);
        uint2 u7 = __ldg(&xin[(long)s7 * VEC + lane]);
        acc4(a0, h4_to_f4(u0)); acc4(a1, h4_to_f4(u1));
        acc4(a2, h4_to_f4(u2)); acc4(a3, h4_to_f4(u3));
        acc4(a0, h4_to_f4(u4)); acc4(a1, h4_to_f4(u5));
        acc4(a2, h4_to_f4(u6)); acc4(a3, h4_to_f4(u7));
    }
    for (; i + 3 < end; i += 4) {
        int s0 = csr[i], s1 = csr[i+1], s2 = csr[i+2], s3 = csr[i+3];
        uint2 u0 = __ldg(&xin[(long)s0 * VEC + lane]);
        uint2 u1 = __ldg(&xin[(long)s1 * VEC + lane]);
        uint2 u2 = __ldg(&xin[(long)s2 * VEC + lane]);
        uint2 u3 = __ldg(&xin[(long)s3 * VEC + lane]);
        acc4(a0, h4_to_f4(u0)); acc4(a1, h4_to_f4(u1));
        acc4(a2, h4_to_f4(u2)); acc4(a3, h4_to_f4(u3));
    }
    for (; i < end; ++i) {
        int s = csr[i];
        acc4(a0, h4_to_f4(__ldg(&xin[(long)s * VEC + lane])));
    }
    float sc = __ldg(&invdeg[w]);
    float4 r;
    r.x = (a0.x + a1.x + a2.x + a3.x) * sc;
    r.y = (a0.y + a1.y + a2.y + a3.y) * sc;
    r.z = (a0.z + a1.z + a2.z + a3.z) * sc;
    r.w = (a0.w + a1.w + a2.w + a3.w) * sc;
    return r;
}

// Layers 1 & 2: xout (fp16) = A~ @ xin (fp16)
__global__ void __launch_bounds__(256)
layer_kernel(const int* __restrict__ rowptr, const int* __restrict__ csr,
             const float* __restrict__ invdeg,
             const uint2* __restrict__ xin, uint2* __restrict__ xout) {
    int w = (blockIdx.x * blockDim.x + threadIdx.x) >> 5;
    int lane = threadIdx.x & 31;
    if (w >= N_NODES) return;
    float4 r = row_mean_h(rowptr, csr, invdeg, xin, w, lane);
    __stcs(&xout[(long)w * VEC + lane], f4_to_h4(r));
}

// Layer 3 fused finale: r = A~ @ x2 (regs only); out = 0.25*(x0_fp32+x1+x2+r)
__global__ void __launch_bounds__(256)
layer3_kernel(const int* __restrict__ rowptr, const int* __restrict__ csr,
              const float* __restrict__ invdeg,
              const float4* __restrict__ ue, const float4* __restrict__ ie,
              const uint2* __restrict__ x1, const uint2* __restrict__ x2,
              float4* __restrict__ out) {
    int w = (blockIdx.x * blockDim.x + threadIdx.x) >> 5;
    int lane = threadIdx.x & 31;
    if (w >= N_NODES) return;
    float4 r = row_mean_h(rowptr, csr, invdeg, x2, w, lane);
    long o = (long)w * VEC + lane;
    float4 v0 = (w < N_USERS) ? __ldcs(&ue[o]) : __ldcs(&ie[o - (long)N_USERS * VEC]);
    float4 v1 = h4_to_f4(__ldcs(&x1[o]));
    float4 v2 = h4_to_f4(__ldg(&x2[o]));      // hot in L2 (gather table)
    float4 ov;
    ov.x = 0.25f * (v0.x + v1.x + v2.x + r.x);
    ov.y = 0.25f * (v0.y + v1.y + v2.y + r.y);
    ov.z = 0.25f * (v0.z + v1.z + v2.z + r.z);
    ov.w = 0.25f * (v0.w + v1.w + v2.w + r.w);
    __stcs(&out[o], ov);
}

extern "C" void kernel_launch(void* const* d_in, const int* in_sizes, int n_in,
                              void* d_out, int out_size) {
    const float* ue = (const float*)d_in[0];           // [N_USERS, 128]
    const float* ie = (const float*)d_in[1];           // [N_ITEMS, 128]
    const int*   ei = (const int*)d_in[2];             // [2, N_EDGES] int32
    const int* src = ei;
    const int* dst = ei + N_EDGES;
    float* out = (float*)d_out;                        // [N_NODES, 128] fp32

    uint2 *x0h, *x1, *x2;
    float *invdeg;
    int *deg, *scanned, *blocksum, *blockoff, *rowptr, *cursor, *csr;
    cudaGetSymbolAddress((void**)&x0h, g_x0h);
    cudaGetSymbolAddress((void**)&x1, g_x1);
    cudaGetSymbolAddress((void**)&x2, g_x2);
    cudaGetSymbolAddress((void**)&invdeg, g_invdeg);
    cudaGetSymbolAddress((void**)&deg, g_deg);
    cudaGetSymbolAddress((void**)&scanned, g_scanned);
    cudaGetSymbolAddress((void**)&blocksum, g_blocksum);
    cudaGetSymbolAddress((void**)&blockoff, g_blockoff);
    cudaGetSymbolAddress((void**)&rowptr, g_rowptr);
    cudaGetSymbolAddress((void**)&cursor, g_cursor);
    cudaGetSymbolAddress((void**)&csr, g_csr);

    const int BT = 256;
    const long nvec = (long)N_NODES * VEC;

    // ---- CSR build + x0 fp16 conversion ----
    cudaMemsetAsync(deg, 0, N_NODES * sizeof(int));
    hist_kernel<<<(N_EDGES + BT - 1) / BT, BT>>>(dst, deg);
    convert_kernel<<<(int)((nvec + BT - 1) / BT), BT>>>(
        (const float4*)ue, (const float4*)ie, x0h);
    scan1_kernel<<<SCAN_BLOCKS, SCAN_BT>>>(deg, scanned, blocksum, invdeg);
    scan2_kernel<<<1, 1024>>>(blocksum, blockoff);
    scan3_kernel<<<(N_NODES + BT - 1) / BT, BT>>>(scanned, blockoff, rowptr, cursor);
    permute_kernel<<<(N_EDGES + BT - 1) / BT, BT>>>(src, dst, cursor, csr);

    // ---- 3 propagation layers (warp per node) ----
    const int blocks = (N_NODES * 32 + BT - 1) / BT;
    layer_kernel<<<blocks, BT>>>(rowptr, csr, invdeg, x0h, x1);
    layer_kernel<<<blocks, BT>>>(rowptr, csr, invdeg, x1, x2);
    layer3_kernel<<<blocks, BT>>>(rowptr, csr, invdeg,
                                  (const float4*)ue, (const float4*)ie,
                                  x1, x2, (float4*)out);
}